// round 1
// baseline (speedup 1.0000x reference)
#include <cuda_runtime.h>

// out[b,l,d] = sum_{i,j} x0[b,i,d] * x1[b,j,d] * filters[i*64+j, l]
// B=2048, F1=F2=64, D=16, L=16
//
// Mapping: n = (b,d) column (32768 total). Block handles 8 batches = 128 n.
// 256 threads = 32 n-quads x 8 j-groups (j-range 8 each); per-thread tile
// 16 l x 4 n held as 32 f32x2 accumulators (fma.rn.f32x2 -> FFMA2, 2x fp32 rate).
// Filters streamed via smem in 4 chunks of 16 i-rows (64KB). Partial sums over
// the 8 j-groups reduced through smem (reusing the filter buffer).

#define BB 8
#define NTHREADS 256
#define BSTR 1040                 // padded batch stride (floats) for bank-conflict-free float4 LDS
#define XSZ (BB * BSTR)           // 8320 floats
#define X1_OFF XSZ
#define FILT_OFF (2 * XSZ)        // 16640
#define FILT_SZ (16 * 64 * 16)    // 16384 floats = 64KB chunk (16 i-rows)
#define SMEM_FLOATS (FILT_OFF + FILT_SZ)   // 33024
#define SMEM_BYTES (SMEM_FLOATS * 4)       // 132096

typedef unsigned long long u64;

__device__ __forceinline__ u64 pk2(float x) {
    u64 r; asm("mov.b64 %0, {%1, %1};" : "=l"(r) : "f"(x)); return r;
}
__device__ __forceinline__ void fma2(u64 &d, u64 a, u64 b) {
    asm("fma.rn.f32x2 %0, %1, %2, %0;" : "+l"(d) : "l"(a), "l"(b));
}
__device__ __forceinline__ float2 up2(u64 v) {
    float2 r; asm("mov.b64 {%0, %1}, %2;" : "=f"(r.x), "=f"(r.y) : "l"(v)); return r;
}

__global__ void __launch_bounds__(NTHREADS, 1)
efm_kernel(const float* __restrict__ x0g, const float* __restrict__ x1g,
           const float* __restrict__ filtg, float* __restrict__ outg)
{
    extern __shared__ float smem[];
    float* x0s = smem;
    float* x1s = smem + X1_OFF;
    float* fs  = smem + FILT_OFF;

    const int tid = threadIdx.x;
    const int b0  = blockIdx.x * BB;

    // ---- Stage x0/x1 for 8 batches into smem with padded batch stride ----
    {
        const float4* g0 = (const float4*)(x0g + b0 * 1024);
        const float4* g1 = (const float4*)(x1g + b0 * 1024);
        float4* s0 = (float4*)x0s;
        float4* s1 = (float4*)x1s;
        #pragma unroll
        for (int k = 0; k < 8; k++) {
            int m = tid + k * NTHREADS;      // 0..2047 float4s
            int b = m >> 8, r = m & 255;     // 256 float4 per batch
            s0[b * (BSTR / 4) + r] = g0[m];
            s1[b * (BSTR / 4) + r] = g1[m];
        }
    }

    const int nq = tid & 31;        // n-quad 0..31
    const int g  = tid >> 5;        // j-group 0..7 (== warp id)
    const int b  = nq >> 2;         // local batch 0..7
    const int d0 = (nq & 3) << 2;   // d offset 0,4,8,12

    const float* x0p = x0s + b * BSTR + d0;
    const float* x1p = x1s + b * BSTR + d0;

    u64 acc[4][8];
    #pragma unroll
    for (int n = 0; n < 4; n++)
        #pragma unroll
        for (int p = 0; p < 8; p++) acc[n][p] = 0ULL;

    // ---- Main loop: 4 filter chunks of 16 i-rows each ----
    for (int ic = 0; ic < 4; ic++) {
        __syncthreads();   // protect fs from previous chunk's readers
        {
            const float4* gf = (const float4*)(filtg + ic * FILT_SZ);
            float4* sf = (float4*)fs;
            #pragma unroll
            for (int k = 0; k < 16; k++)
                sf[tid + k * NTHREADS] = gf[tid + k * NTHREADS];
        }
        __syncthreads();

        #pragma unroll 1
        for (int ii = 0; ii < 16; ii++) {
            const int i = ic * 16 + ii;
            const float4 a = *(const float4*)(x0p + i * 16);
            const float* wbase = fs + ii * 1024 + g * 128;   // (ii*64 + g*8)*16

            #pragma unroll
            for (int jj = 0; jj < 8; jj++) {
                const int j = g * 8 + jj;
                const float4 c = *(const float4*)(x1p + j * 16);

                const ulonglong2* wp = (const ulonglong2*)(wbase + jj * 16);
                ulonglong2 wa = wp[0], wb = wp[1], wc = wp[2], wd = wp[3];
                u64 w[8] = {wa.x, wa.y, wb.x, wb.y, wc.x, wc.y, wd.x, wd.y};

                u64 q[4];
                q[0] = pk2(a.x * c.x);
                q[1] = pk2(a.y * c.y);
                q[2] = pk2(a.z * c.z);
                q[3] = pk2(a.w * c.w);

                #pragma unroll
                for (int n = 0; n < 4; n++)
                    #pragma unroll
                    for (int p = 0; p < 8; p++)
                        fma2(acc[n][p], w[p], q[n]);
            }
        }
    }

    // ---- Reduce the 8 j-group partials through smem (reuse filter buffer) ----
    __syncthreads();
    float* red = fs;   // [g][l][128 n] : g*2048 + l*128 + n
    #pragma unroll
    for (int p = 0; p < 8; p++)
        #pragma unroll
        for (int n = 0; n < 4; n++) {
            float2 v = up2(acc[n][p]);
            red[g * 2048 + (2 * p)     * 128 + nq * 4 + n] = v.x;
            red[g * 2048 + (2 * p + 1) * 128 + nq * 4 + n] = v.y;
        }
    __syncthreads();

    #pragma unroll
    for (int k = 0; k < 8; k++) {
        int idx = tid + k * NTHREADS;   // 0..2047 = 16 l x 128 n
        int l = idx >> 7, n = idx & 127;
        float s = 0.f;
        #pragma unroll
        for (int gg = 0; gg < 8; gg++) s += red[gg * 2048 + l * 128 + n];
        outg[(b0 + (n >> 4)) * 256 + l * 16 + (n & 15)] = s;
    }
}

extern "C" void kernel_launch(void* const* d_in, const int* in_sizes, int n_in,
                              void* d_out, int out_size)
{
    const float* x0   = (const float*)d_in[0];   // [2048, 64, 16]
    const float* x1   = (const float*)d_in[1];   // [2048, 64, 16]
    const float* filt = (const float*)d_in[2];   // [1, 4096, 16]
    float* out        = (float*)d_out;           // [2048, 16, 16]

    cudaFuncSetAttribute(efm_kernel, cudaFuncAttributeMaxDynamicSharedMemorySize, SMEM_BYTES);
    efm_kernel<<<2048 / BB, NTHREADS, SMEM_BYTES>>>(x0, x1, filt, out);
}